// round 1
// baseline (speedup 1.0000x reference)
#include <cuda_runtime.h>

// Problem constants
#define BB 2
#define SS 1024
#define HH 8
#define DD 64
#define RR 32
#define KW 128
#define CC (HH*DD)        // 512 channels
#define ZLEN (4*KW+SS)    // 1536
#define TS 64             // s-tile per CTA
#define RH 16             // r rows per CTA
#define ZWIN (TS+KW)      // 192 loaded (191 needed)
#define ZSTRIDE 196       // padded row stride (words); 196 % 32 == 4 -> conflict-free
#define NTHREADS 128

// smem (static, 46.3 KB total)
__global__ __launch_bounds__(NTHREADS, 4)
void convspe_kernel(const float* __restrict__ qg,
                    const float* __restrict__ kg,
                    const float* __restrict__ wq,
                    const float* __restrict__ wk,
                    const float* __restrict__ zg,
                    float* __restrict__ out)
{
    __shared__ float z_sm[RH * ZSTRIDE];     // 16 x 196
    __shared__ float q_sm[TS * DD];          // 64 x 64
    __shared__ float k_sm[TS * DD];          // 64 x 64
    __shared__ float wq_sm[KW];
    __shared__ float wk_sm[KW];

    const int tid   = threadIdx.x;
    const int stile = blockIdx.x;            // 0..15
    const int h     = blockIdx.y;            // 0..7
    const int bz    = blockIdx.z;            // 0..3
    const int b     = bz >> 1;
    const int r0    = (bz & 1) * RH;
    const int s0    = stile * TS;

    // ---- stage q/k tiles once (coalesced: d contiguous) ----
    // 64 rows x 16 float4 per tensor = 1024 float4 each
    for (int idx = tid; idx < TS * DD / 4; idx += NTHREADS) {
        int row = idx >> 4;          // 0..63
        int c4  = idx & 15;          // 0..15
        int goff = (((b * SS + s0 + row) * HH + h) * DD) + c4 * 4;
        reinterpret_cast<float4*>(q_sm)[idx] =
            *reinterpret_cast<const float4*>(qg + goff);
        reinterpret_cast<float4*>(k_sm)[idx] =
            *reinterpret_cast<const float4*>(kg + goff);
    }

    const int r  = tid & 15;         // 0..15  (z row)
    const int sg = tid >> 4;         // 0..7   (s group)
    const int i0 = sg * 8;

    float accq[8], acck[8];
    #pragma unroll
    for (int i = 0; i < 8; i++) { accq[i] = 0.f; acck[i] = 0.f; }

    for (int d = 0; d < DD; d++) {
        const int c = h * DD + d;

        __syncthreads();   // protect z_sm / w_sm reuse (also covers q/k staging on d==0)

        // ---- stage both weight rows for channel c (256 floats) ----
        if (tid < 64) {
            int which = tid >> 5;               // 0 -> wq, 1 -> wk
            int j     = (tid & 31) * 4;
            const float* wsrc = which ? wk : wq;
            float*       wdst = which ? wk_sm : wq_sm;
            *reinterpret_cast<float4*>(wdst + j) =
                *reinterpret_cast<const float4*>(wsrc + c * KW + j);
        }

        // ---- stage z window: rows r0..r0+15, cols K+s0 .. K+s0+191 ----
        // 16 rows x 48 float4 = 768 float4; always in-bounds (max index 1279 < 1536)
        for (int idx = tid; idx < RH * (ZWIN / 4); idx += NTHREADS) {
            int row = idx / (ZWIN / 4);          // /48
            int c4  = idx - row * (ZWIN / 4);    // %48
            int goff = ((b * RR + r0 + row) * CC + c) * ZLEN + (KW + s0) + c4 * 4;
            *reinterpret_cast<float4*>(z_sm + row * ZSTRIDE + c4 * 4) =
                *reinterpret_cast<const float4*>(zg + goff);
        }
        __syncthreads();

        // ---- register-sliding-window depthwise conv, both filters ----
        const float* zrow = z_sm + r * ZSTRIDE + i0;
        float cq[8], ck[8];
        #pragma unroll
        for (int i = 0; i < 8; i++) { cq[i] = 0.f; ck[i] = 0.f; }

        float za[8], zb[8];
        *reinterpret_cast<float4*>(za)     = *reinterpret_cast<const float4*>(zrow);
        *reinterpret_cast<float4*>(za + 4) = *reinterpret_cast<const float4*>(zrow + 4);

        #pragma unroll
        for (int tc = 0; tc < 16; tc++) {
            *reinterpret_cast<float4*>(zb) =
                *reinterpret_cast<const float4*>(zrow + (tc + 1) * 8);
            *reinterpret_cast<float4*>(zb + 4) =
                *reinterpret_cast<const float4*>(zrow + (tc + 1) * 8 + 4);
            #pragma unroll
            for (int tt = 0; tt < 8; tt++) {
                float wkv = wk_sm[tc * 8 + tt];   // conv(z, wk) -> pairs with queries
                float wqv = wq_sm[tc * 8 + tt];   // conv(z, wq) -> pairs with keys
                #pragma unroll
                for (int ii = 0; ii < 8; ii++) {
                    float zv = (tt + ii < 8) ? za[tt + ii] : zb[tt + ii - 8];
                    cq[ii] = fmaf(wkv, zv, cq[ii]);
                    ck[ii] = fmaf(wqv, zv, ck[ii]);
                }
            }
            #pragma unroll
            for (int i = 0; i < 8; i++) za[i] = zb[i];
        }

        // ---- epilogue: scale by q/k at (s, d) and accumulate over d ----
        #pragma unroll
        for (int ii = 0; ii < 8; ii++) {
            float qv = q_sm[(i0 + ii) * DD + d];
            float kv = k_sm[(i0 + ii) * DD + d];
            accq[ii] = fmaf(cq[ii], qv, accq[ii]);
            acck[ii] = fmaf(ck[ii], kv, acck[ii]);
        }
    }

    // ---- write qhat then khat, each (B,S,H,R) row-major ----
    const int khat_off = BB * SS * HH * RR;
    #pragma unroll
    for (int ii = 0; ii < 8; ii++) {
        int s = s0 + i0 + ii;
        int o = ((b * SS + s) * HH + h) * RR + (r0 + r);
        out[o]            = accq[ii];
        out[khat_off + o] = acck[ii];
    }
}

extern "C" void kernel_launch(void* const* d_in, const int* in_sizes, int n_in,
                              void* d_out, int out_size)
{
    const float* queries = (const float*)d_in[0];
    const float* keys    = (const float*)d_in[1];
    const float* wq      = (const float*)d_in[2];
    const float* wk      = (const float*)d_in[3];
    const float* z       = (const float*)d_in[4];
    float* out = (float*)d_out;

    dim3 grid(SS / TS, HH, BB * 2);   // 16 x 8 x 4 = 512 CTAs
    dim3 block(NTHREADS);
    convspe_kernel<<<grid, block>>>(queries, keys, wq, wk, z, out);
}

// round 2
// speedup vs baseline: 1.0398x; 1.0398x over previous
#include <cuda_runtime.h>

typedef unsigned long long u64;

// Problem constants
#define BB 2
#define SS 1024
#define HH 8
#define DD 64
#define RR 32
#define KW 128
#define CC (HH*DD)        // 512 channels
#define ZLEN (4*KW+SS)    // 1536
#define TS 64             // s-tile per CTA
#define RH 16             // r rows per CTA
#define ZWIN (TS+KW)      // 192 loaded (191 needed)
#define ZSTRIDE 196       // padded row stride (words); 16B-aligned rows
#define NTHREADS 128

// ---- packed fp32x2 helpers (Blackwell FFMA2 path) ----
__device__ __forceinline__ u64 bcast2(float x) {
    u64 r; asm("mov.b64 %0, {%1, %1};" : "=l"(r) : "f"(x)); return r;
}
__device__ __forceinline__ void fma2(u64 &d, u64 a, u64 b) {
    // d.lo += a.lo*b.lo ; d.hi += a.hi*b.hi   (exact fp32 FMA per lane)
    asm("fma.rn.f32x2 %0, %1, %2, %0;" : "+l"(d) : "l"(a), "l"(b));
}
__device__ __forceinline__ float2 unpack2(u64 v) {
    float2 f; asm("mov.b64 {%0, %1}, %2;" : "=f"(f.x), "=f"(f.y) : "l"(v)); return f;
}

__global__ __launch_bounds__(NTHREADS, 4)
void convspe_kernel(const float* __restrict__ qg,
                    const float* __restrict__ kg,
                    const float* __restrict__ wq,
                    const float* __restrict__ wk,
                    const float* __restrict__ zg,
                    float* __restrict__ out)
{
    __shared__ __align__(16) float z_sm[RH * ZSTRIDE];   // 12.25 KB
    __shared__ __align__(16) float qk_sm[TS * DD * 2];   // 32 KB, interleaved (q,k)
    __shared__ __align__(16) float w2_sm[KW * 2];        // 1 KB, interleaved (wk,wq)

    const int tid   = threadIdx.x;
    const int stile = blockIdx.x;            // 0..15
    const int h     = blockIdx.y;            // 0..7
    const int bz    = blockIdx.z;            // 0..3
    const int b     = bz >> 1;
    const int r0    = (bz & 1) * RH;
    const int s0    = stile * TS;

    // ---- stage q/k tiles once, interleaved per (s,d): qk_sm[2*(s*D+d)] = {q,k} ----
    for (int idx = tid; idx < TS * DD / 4; idx += NTHREADS) {
        int row = idx >> 4;          // 0..63
        int c4  = idx & 15;          // 0..15
        int goff = (((b * SS + s0 + row) * HH + h) * DD) + c4 * 4;
        float4 q4 = *reinterpret_cast<const float4*>(qg + goff);
        float4 k4 = *reinterpret_cast<const float4*>(kg + goff);
        float2* dst = reinterpret_cast<float2*>(qk_sm) + row * DD + c4 * 4;
        dst[0] = make_float2(q4.x, k4.x);
        dst[1] = make_float2(q4.y, k4.y);
        dst[2] = make_float2(q4.z, k4.z);
        dst[3] = make_float2(q4.w, k4.w);
    }

    const int r  = tid & 15;         // 0..15  (z row)
    const int sg = tid >> 4;         // 0..7   (s group)
    const int i0 = sg * 8;

    u64 acc2d[8];                    // (accq, acck) pairs over d
    #pragma unroll
    for (int i = 0; i < 8; i++) acc2d[i] = 0ULL;   // bit pattern of (0.f, 0.f)

    for (int d = 0; d < DD; d++) {
        const int c = h * DD + d;

        __syncthreads();   // protect z_sm / w2_sm reuse (also covers qk staging on d==0)

        // ---- stage interleaved weight pairs: w2_sm[2t] = wk[c][t], w2_sm[2t+1] = wq[c][t] ----
        {
            float wkv = wk[c * KW + tid];     // coalesced across tid
            float wqv = wq[c * KW + tid];
            w2_sm[2 * tid]     = wkv;         // lo pairs with queries (cq += wk*z)
            w2_sm[2 * tid + 1] = wqv;         // hi pairs with keys    (ck += wq*z)
        }

        // ---- stage z window: rows r0..r0+15, cols K+s0 .. K+s0+191 ----
        for (int idx = tid; idx < RH * (ZWIN / 4); idx += NTHREADS) {
            int row = idx / (ZWIN / 4);          // /48
            int c4  = idx - row * (ZWIN / 4);    // %48
            int goff = ((b * RR + r0 + row) * CC + c) * ZLEN + (KW + s0) + c4 * 4;
            *reinterpret_cast<float4*>(z_sm + row * ZSTRIDE + c4 * 4) =
                *reinterpret_cast<const float4*>(zg + goff);
        }
        __syncthreads();

        const float* zrow = z_sm + r * ZSTRIDE + i0;   // 16B aligned
        const u64*   w2p  = reinterpret_cast<const u64*>(w2_sm);

        u64 c2[8];                       // per-d conv accumulators (cq, ck)
        #pragma unroll
        for (int i = 0; i < 8; i++) c2[i] = 0ULL;

        // ---- init broadcast window zz[0..14] = (z[p], z[p]) for p = 0..14 ----
        u64 zz[15];
        float carry;
        {
            float4 a0 = *reinterpret_cast<const float4*>(zrow);
            float4 a1 = *reinterpret_cast<const float4*>(zrow + 4);
            float4 a2 = *reinterpret_cast<const float4*>(zrow + 8);
            float4 a3 = *reinterpret_cast<const float4*>(zrow + 12);
            zz[0]=bcast2(a0.x);  zz[1]=bcast2(a0.y);  zz[2]=bcast2(a0.z);  zz[3]=bcast2(a0.w);
            zz[4]=bcast2(a1.x);  zz[5]=bcast2(a1.y);  zz[6]=bcast2(a1.z);  zz[7]=bcast2(a1.w);
            zz[8]=bcast2(a2.x);  zz[9]=bcast2(a2.y);  zz[10]=bcast2(a2.z); zz[11]=bcast2(a2.w);
            zz[12]=bcast2(a3.x); zz[13]=bcast2(a3.y); zz[14]=bcast2(a3.z);
            carry = a3.w;
        }

        #pragma unroll
        for (int tc = 0; tc < 16; tc++) {
            // prefetch next 8 z values (aligned LDS.128) while FMAs run
            float4 n0, n1;
            if (tc < 15) {
                n0 = *reinterpret_cast<const float4*>(zrow + tc * 8 + 16);
                n1 = *reinterpret_cast<const float4*>(zrow + tc * 8 + 20);
            }

            #pragma unroll
            for (int tt = 0; tt < 8; tt++) {
                u64 w2v = w2p[tc * 8 + tt];          // (wk[t], wq[t]) single LDS.64
                #pragma unroll
                for (int ii = 0; ii < 8; ii++)
                    fma2(c2[ii], w2v, zz[tt + ii]);  // 2 FMAs per instruction
            }

            if (tc < 15) {
                #pragma unroll
                for (int p = 0; p < 7; p++) zz[p] = zz[p + 8];   // renamed away by unroll
                zz[7]  = bcast2(carry);
                zz[8]  = bcast2(n0.x); zz[9]  = bcast2(n0.y);
                zz[10] = bcast2(n0.z); zz[11] = bcast2(n0.w);
                zz[12] = bcast2(n1.x); zz[13] = bcast2(n1.y);
                zz[14] = bcast2(n1.z);
                carry  = n1.w;
            }
        }

        // ---- epilogue: acc2d += c2 * (q, k) — one LDS.64 + one FFMA2 per s ----
        const u64* qkp = reinterpret_cast<const u64*>(qk_sm);
        #pragma unroll
        for (int ii = 0; ii < 8; ii++) {
            u64 qkv = qkp[(i0 + ii) * DD + d];
            fma2(acc2d[ii], c2[ii], qkv);
        }
    }

    // ---- write qhat then khat, each (B,S,H,R) row-major ----
    const int khat_off = BB * SS * HH * RR;
    #pragma unroll
    for (int ii = 0; ii < 8; ii++) {
        int s = s0 + i0 + ii;
        int o = ((b * SS + s) * HH + h) * RR + (r0 + r);
        float2 v = unpack2(acc2d[ii]);
        out[o]            = v.x;   // qhat (conv wk paired with queries)
        out[khat_off + o] = v.y;   // khat (conv wq paired with keys)
    }
}

extern "C" void kernel_launch(void* const* d_in, const int* in_sizes, int n_in,
                              void* d_out, int out_size)
{
    const float* queries = (const float*)d_in[0];
    const float* keys    = (const float*)d_in[1];
    const float* wq      = (const float*)d_in[2];
    const float* wk      = (const float*)d_in[3];
    const float* z       = (const float*)d_in[4];
    float* out = (float*)d_out;

    dim3 grid(SS / TS, HH, BB * 2);   // 16 x 8 x 4 = 512 CTAs
    dim3 block(NTHREADS);
    convspe_kernel<<<grid, block>>>(queries, keys, wq, wk, z, out);
}

// round 3
// speedup vs baseline: 1.0422x; 1.0023x over previous
#include <cuda_runtime.h>

typedef unsigned long long u64;

// Problem constants
#define BB 2
#define SS 1024
#define HH 8
#define DD 64
#define RR 32
#define KW 128
#define CC (HH*DD)        // 512 channels
#define ZLEN (4*KW+SS)    // 1536
#define TS 64             // s-tile per CTA
#define RH 16             // r rows per CTA
#define ZWIN (TS+KW)      // 192 loaded (191 needed)
#define ZSTRIDE 196       // padded row stride (words); 16B-aligned rows
#define NTHREADS 128

// ---- packed fp32x2 helpers (Blackwell FFMA2 path) ----
__device__ __forceinline__ u64 bcast2(float x) {
    u64 r; asm("mov.b64 %0, {%1, %1};" : "=l"(r) : "f"(x)); return r;
}
__device__ __forceinline__ void fma2(u64 &d, u64 a, u64 b) {
    // d.lo += a.lo*b.lo ; d.hi += a.hi*b.hi   (exact fp32 FMA per lane)
    asm("fma.rn.f32x2 %0, %1, %2, %0;" : "+l"(d) : "l"(a), "l"(b));
}
__device__ __forceinline__ float2 unpack2(u64 v) {
    float2 f; asm("mov.b64 {%0, %1}, %2;" : "=f"(f.x), "=f"(f.y) : "l"(v)); return f;
}

__global__ __launch_bounds__(NTHREADS, 4)
void convspe_kernel(const float* __restrict__ qg,
                    const float* __restrict__ kg,
                    const float* __restrict__ wq,
                    const float* __restrict__ wk,
                    const float* __restrict__ zg,
                    float* __restrict__ out)
{
    __shared__ __align__(16) float z_sm[RH * ZSTRIDE];   // 12.25 KB
    __shared__ __align__(16) float qk_sm[TS * DD * 2];   // 32 KB, interleaved (q,k)
    __shared__ __align__(16) float w2_sm[KW * 2];        // 1 KB, interleaved (wk,wq)

    const int tid   = threadIdx.x;
    const int stile = blockIdx.x;            // 0..15
    const int h     = blockIdx.y;            // 0..7
    const int bz    = blockIdx.z;            // 0..3
    const int b     = bz >> 1;
    const int r0    = (bz & 1) * RH;
    const int s0    = stile * TS;

    // ---- stage q/k tiles once, interleaved per (s,d): qk_sm[2*(s*D+d)] = {q,k} ----
    for (int idx = tid; idx < TS * DD / 4; idx += NTHREADS) {
        int row = idx >> 4;          // 0..63
        int c4  = idx & 15;          // 0..15
        int goff = (((b * SS + s0 + row) * HH + h) * DD) + c4 * 4;
        float4 q4 = *reinterpret_cast<const float4*>(qg + goff);
        float4 k4 = *reinterpret_cast<const float4*>(kg + goff);
        float2* dst = reinterpret_cast<float2*>(qk_sm) + row * DD + c4 * 4;
        dst[0] = make_float2(q4.x, k4.x);
        dst[1] = make_float2(q4.y, k4.y);
        dst[2] = make_float2(q4.z, k4.z);
        dst[3] = make_float2(q4.w, k4.w);
    }

    const int r  = tid & 15;         // 0..15  (z row)
    const int sg = tid >> 4;         // 0..7   (s group)
    const int i0 = sg * 8;

    u64 acc2d[8];                    // (accq, acck) pairs over d
    #pragma unroll
    for (int i = 0; i < 8; i++) acc2d[i] = 0ULL;   // bit pattern of (0.f, 0.f)

    for (int d = 0; d < DD; d++) {
        const int c = h * DD + d;

        __syncthreads();   // protect z_sm / w2_sm reuse (also covers qk staging on d==0)

        // ---- stage interleaved weight pairs: w2_sm[2t] = wk[c][t], w2_sm[2t+1] = wq[c][t] ----
        {
            float wkv = wk[c * KW + tid];     // coalesced across tid
            float wqv = wq[c * KW + tid];
            w2_sm[2 * tid]     = wkv;         // lo pairs with queries (cq += wk*z)
            w2_sm[2 * tid + 1] = wqv;         // hi pairs with keys    (ck += wq*z)
        }

        // ---- stage z window: rows r0..r0+15, cols K+s0 .. K+s0+191 ----
        for (int idx = tid; idx < RH * (ZWIN / 4); idx += NTHREADS) {
            int row = idx / (ZWIN / 4);          // /48
            int c4  = idx - row * (ZWIN / 4);    // %48
            int goff = ((b * RR + r0 + row) * CC + c) * ZLEN + (KW + s0) + c4 * 4;
            *reinterpret_cast<float4*>(z_sm + row * ZSTRIDE + c4 * 4) =
                *reinterpret_cast<const float4*>(zg + goff);
        }
        __syncthreads();

        const float* zrow = z_sm + r * ZSTRIDE + i0;   // 16B aligned
        const u64*   w2p  = reinterpret_cast<const u64*>(w2_sm);

        u64 c2[8];                       // per-d conv accumulators (cq, ck)
        #pragma unroll
        for (int i = 0; i < 8; i++) c2[i] = 0ULL;

        // ---- init broadcast window zz[0..14] = (z[p], z[p]) for p = 0..14 ----
        u64 zz[15];
        float carry;
        {
            float4 a0 = *reinterpret_cast<const float4*>(zrow);
            float4 a1 = *reinterpret_cast<const float4*>(zrow + 4);
            float4 a2 = *reinterpret_cast<const float4*>(zrow + 8);
            float4 a3 = *reinterpret_cast<const float4*>(zrow + 12);
            zz[0]=bcast2(a0.x);  zz[1]=bcast2(a0.y);  zz[2]=bcast2(a0.z);  zz[3]=bcast2(a0.w);
            zz[4]=bcast2(a1.x);  zz[5]=bcast2(a1.y);  zz[6]=bcast2(a1.z);  zz[7]=bcast2(a1.w);
            zz[8]=bcast2(a2.x);  zz[9]=bcast2(a2.y);  zz[10]=bcast2(a2.z); zz[11]=bcast2(a2.w);
            zz[12]=bcast2(a3.x); zz[13]=bcast2(a3.y); zz[14]=bcast2(a3.z);
            carry = a3.w;
        }

        #pragma unroll
        for (int tc = 0; tc < 16; tc++) {
            // prefetch next 8 z values (aligned LDS.128) while FMAs run
            float4 n0, n1;
            if (tc < 15) {
                n0 = *reinterpret_cast<const float4*>(zrow + tc * 8 + 16);
                n1 = *reinterpret_cast<const float4*>(zrow + tc * 8 + 20);
            }

            #pragma unroll
            for (int tt = 0; tt < 8; tt++) {
                u64 w2v = w2p[tc * 8 + tt];          // (wk[t], wq[t]) single LDS.64
                #pragma unroll
                for (int ii = 0; ii < 8; ii++)
                    fma2(c2[ii], w2v, zz[tt + ii]);  // 2 FMAs per instruction
            }

            if (tc < 15) {
                #pragma unroll
                for (int p = 0; p < 7; p++) zz[p] = zz[p + 8];   // renamed away by unroll
                zz[7]  = bcast2(carry);
                zz[8]  = bcast2(n0.x); zz[9]  = bcast2(n0.y);
                zz[10] = bcast2(n0.z); zz[11] = bcast2(n0.w);
                zz[12] = bcast2(n1.x); zz[13] = bcast2(n1.y);
                zz[14] = bcast2(n1.z);
                carry  = n1.w;
            }
        }

        // ---- epilogue: acc2d += c2 * (q, k) — one LDS.64 + one FFMA2 per s ----
        const u64* qkp = reinterpret_cast<const u64*>(qk_sm);
        #pragma unroll
        for (int ii = 0; ii < 8; ii++) {
            u64 qkv = qkp[(i0 + ii) * DD + d];
            fma2(acc2d[ii], c2[ii], qkv);
        }
    }

    // ---- write qhat then khat, each (B,S,H,R) row-major ----
    const int khat_off = BB * SS * HH * RR;
    #pragma unroll
    for (int ii = 0; ii < 8; ii++) {
        int s = s0 + i0 + ii;
        int o = ((b * SS + s) * HH + h) * RR + (r0 + r);
        float2 v = unpack2(acc2d[ii]);
        out[o]            = v.x;   // qhat (conv wk paired with queries)
        out[khat_off + o] = v.y;   // khat (conv wq paired with keys)
    }
}

extern "C" void kernel_launch(void* const* d_in, const int* in_sizes, int n_in,
                              void* d_out, int out_size)
{
    const float* queries = (const float*)d_in[0];
    const float* keys    = (const float*)d_in[1];
    const float* wq      = (const float*)d_in[2];
    const float* wk      = (const float*)d_in[3];
    const float* z       = (const float*)d_in[4];
    float* out = (float*)d_out;

    dim3 grid(SS / TS, HH, BB * 2);   // 16 x 8 x 4 = 512 CTAs
    dim3 block(NTHREADS);
    convspe_kernel<<<grid, block>>>(queries, keys, wq, wk, z, out);
}